// round 7
// baseline (speedup 1.0000x reference)
#include <cuda_runtime.h>
#include <cuda_bf16.h>

// PCEN: M_t = (1-s) M_{t-1} + s x_t  (per [b,f] row along T),
// out = (x / (EPS + M)^alpha + bias)^power - bias^power
//
// One CTA (128 thr) per row of T=2048; 16 elems/thread.
// Coalesced LDG -> padded SMEM tile -> per-thread contiguous regs,
// scaled linear-recurrence scan (m' = M/s), minimal-instruction epilogue,
// outputs staged back through the tile so STG is coalesced too.
// R7: explicit shared-memory carveout so 16 CTAs/SM fit (occupancy fix).

#define T_LEN 2048
#define NTHREADS 128
#define PER_THREAD 16
#define NWARPS (NTHREADS / 32)
#define ROW_F4 (T_LEN / 4)                 // 512 float4 per row
#define PAD_SLOT(k) ((k) + ((k) >> 3))     // 1 pad float4 per 8
#define TILE_F4 (ROW_F4 + (ROW_F4 >> 3))   // 576

__device__ __forceinline__ float fast_lg2(float x) {
    float r;
    asm("lg2.approx.f32 %0, %1;" : "=f"(r) : "f"(x));
    return r;
}
__device__ __forceinline__ float fast_ex2(float x) {
    float r;
    asm("ex2.approx.f32 %0, %1;" : "=f"(r) : "f"(x));
    return r;
}

__global__ __launch_bounds__(NTHREADS, 10)
void pcen_kernel(const float* __restrict__ x,
                 const float* __restrict__ alpha_p,
                 const float* __restrict__ power_p,
                 const float* __restrict__ bias_p,
                 float* __restrict__ out)
{
    const float s  = 0.015f;
    const float c1 = 0.985f;      // 1 - s
    const float EPSv = 1e-9f;

    __shared__ float4 tile[TILE_F4];
    __shared__ float  sW[NWARPS];

    const int tid  = threadIdx.x;
    const int lane = tid & 31;
    const int warp = tid >> 5;

    // Scalars early (independent loads, in flight before barriers).
    const float alpha = __ldg(alpha_p);
    const float power = __ldg(power_p);
    const float bias  = __ldg(bias_p);

    const size_t base = (size_t)blockIdx.x * T_LEN;
    const float4* xin = (const float4*)(x + base);
    float4* oout = (float4*)(out + base);

    // Fully-coalesced loads (lanes consecutive), front-batched (MLP=4).
    float4 ld0 = xin[0 * NTHREADS + tid];
    float4 ld1 = xin[1 * NTHREADS + tid];
    float4 ld2 = xin[2 * NTHREADS + tid];
    float4 ld3 = xin[3 * NTHREADS + tid];
    tile[PAD_SLOT(0 * NTHREADS + tid)] = ld0;
    tile[PAD_SLOT(1 * NTHREADS + tid)] = ld1;
    tile[PAD_SLOT(2 * NTHREADS + tid)] = ld2;
    tile[PAD_SLOT(3 * NTHREADS + tid)] = ld3;
    __syncthreads();   // bar1: tile(x) ready

    // Per-thread contiguous chunk: elements [tid*16, tid*16+16).
    float xv[PER_THREAD];
    #pragma unroll
    for (int j = 0; j < 4; j++) {
        float4 t4 = tile[PAD_SLOT(tid * 4 + j)];
        xv[4 * j + 0] = t4.x; xv[4 * j + 1] = t4.y;
        xv[4 * j + 2] = t4.z; xv[4 * j + 3] = t4.w;
    }

    // Thread-local scaled recurrence from zero (m' = M/s):
    // two independent 8-chains for ILP, merged with one FMA.
    float b0 = 0.f, b1 = 0.f;
    #pragma unroll
    for (int i = 0; i < 8; i++)  b0 = fmaf(c1, b0, xv[i]);
    #pragma unroll
    for (int i = 8; i < 16; i++) b1 = fmaf(c1, b1, xv[i]);

    // Decay powers.
    const float c2  = c1 * c1;
    const float c4  = c2 * c2;
    const float c8  = c4 * c4;       // c1^8
    const float a1  = c8 * c8;       // c1^16  (per-thread segment decay A)
    const float a2  = a1 * a1;       // A^2
    const float a4  = a2 * a2;       // A^4
    const float a8  = a4 * a4;       // A^8
    const float a16 = a8 * a8;       // A^16
    const float a32 = a16 * a16;     // A^32 (per-warp decay)

    float B = fmaf(b0, c8, b1);      // thread total

    // Inclusive Kogge-Stone warp scan: v_t = v_{t-d} * A^d + v_t
    float v = B;
    float u;
    u = __shfl_up_sync(0xffffffffu, v, 1);  if (lane >= 1)  v = fmaf(u, a1,  v);
    u = __shfl_up_sync(0xffffffffu, v, 2);  if (lane >= 2)  v = fmaf(u, a2,  v);
    u = __shfl_up_sync(0xffffffffu, v, 4);  if (lane >= 4)  v = fmaf(u, a4,  v);
    u = __shfl_up_sync(0xffffffffu, v, 8);  if (lane >= 8)  v = fmaf(u, a8,  v);
    u = __shfl_up_sync(0xffffffffu, v, 16); if (lane >= 16) v = fmaf(u, a16, v);

    if (lane == 31) sW[warp] = v;
    __syncthreads();   // bar2: sW ready; tile(x) fully consumed

    // Cross-warp carry, computed redundantly per-thread (broadcast LDS):
    // carry_w = sum_{w'<w} sW[w'] * A32^(w-1-w')
    float carry = 0.f;
    #pragma unroll
    for (int w = 0; w < NWARPS - 1; w++)
        if (warp > w) carry = fmaf(carry, a32, sW[w]);

    float prev = __shfl_up_sync(0xffffffffu, v, 1);
    if (lane == 0) prev = 0.f;

    // A^lane by exact binary exponentiation.
    float p = 1.f;
    if (lane & 1)  p *= a1;
    if (lane & 2)  p *= a2;
    if (lane & 4)  p *= a4;
    if (lane & 8)  p *= a8;
    if (lane & 16) p *= a16;

    float m = fmaf(carry, p, prev);   // scaled state entering this segment

    const float nalpha = -alpha;
    const float bp = fast_ex2(power * fast_lg2(bias));   // bias^power

    // Epilogue (minimal form): per elem 2 FFMA + lg2/mul/ex2 + FFMA + lg2/mul/ex2 + FADD.
    #pragma unroll
    for (int j = 0; j < 4; j++) {
        float4 o4;
        float o[4];
        #pragma unroll
        for (int e = 0; e < 4; e++) {
            const int i = 4 * j + e;
            m = fmaf(c1, m, xv[i]);                       // m' recurrence
            float arg = fmaf(s, m, EPSv);                 // EPS + M
            float inv = fast_ex2(nalpha * fast_lg2(arg)); // (EPS+M)^(-alpha)
            float z = fmaf(xv[i], inv, bias);
            o[e] = fast_ex2(power * fast_lg2(z)) - bp;
        }
        o4.x = o[0]; o4.y = o[1]; o4.z = o[2]; o4.w = o[3];
        tile[PAD_SLOT(tid * 4 + j)] = o4;                 // stage for coalesced STG
    }
    __syncthreads();   // bar3: tile(o) ready

    oout[0 * NTHREADS + tid] = tile[PAD_SLOT(0 * NTHREADS + tid)];
    oout[1 * NTHREADS + tid] = tile[PAD_SLOT(1 * NTHREADS + tid)];
    oout[2 * NTHREADS + tid] = tile[PAD_SLOT(2 * NTHREADS + tid)];
    oout[3 * NTHREADS + tid] = tile[PAD_SLOT(3 * NTHREADS + tid)];
}

extern "C" void kernel_launch(void* const* d_in, const int* in_sizes, int n_in,
                              void* d_out, int out_size)
{
    const float* x     = (const float*)d_in[0];
    const float* alpha = (const float*)d_in[1];
    const float* power = (const float*)d_in[2];
    const float* bias  = (const float*)d_in[3];
    float* out = (float*)d_out;

    // Ensure the L1/shared carveout admits 16 CTAs/SM (16 x 9.2KB ~= 148KB).
    // Host-side attribute set: not a stream op, graph-capture-safe, no allocation.
    static_assert(sizeof(float4) == 16, "");
    cudaFuncSetAttribute(pcen_kernel,
                         cudaFuncAttributePreferredSharedMemoryCarveout, 75);

    int rows = in_sizes[0] / T_LEN;   // B*F = 16384
    pcen_kernel<<<rows, NTHREADS>>>(x, alpha, power, bias, out);
}

// round 11
// speedup vs baseline: 1.5184x; 1.5184x over previous
#include <cuda_runtime.h>
#include <cuda_bf16.h>
#include <cstdint>

// PCEN: M_t = (1-s) M_{t-1} + s x_t  (per [b,f] row along T),
// out = (x / (EPS + M)^alpha + bias)^power - bias^power
//
// One CTA (128 thr) per row of T=2048; 16 elems/thread.
// R8: GMEM->SMEM via cp.async (no register staging, fewer instrs, lower
// reg pressure -> more CTAs/SM). Padded SMEM tile -> per-thread contiguous
// regs, scaled linear-recurrence scan (m' = M/s), minimal epilogue,
// outputs staged back through the tile for coalesced STG.

#define T_LEN 2048
#define NTHREADS 128
#define PER_THREAD 16
#define NWARPS (NTHREADS / 32)
#define ROW_F4 (T_LEN / 4)                 // 512 float4 per row
#define PAD_SLOT(k) ((k) + ((k) >> 3))     // 1 pad float4 per 8
#define TILE_F4 (ROW_F4 + (ROW_F4 >> 3))   // 576

__device__ __forceinline__ float fast_lg2(float x) {
    float r;
    asm("lg2.approx.f32 %0, %1;" : "=f"(r) : "f"(x));
    return r;
}
__device__ __forceinline__ float fast_ex2(float x) {
    float r;
    asm("ex2.approx.f32 %0, %1;" : "=f"(r) : "f"(x));
    return r;
}
__device__ __forceinline__ unsigned int smem_u32(const void* p) {
    unsigned int a;
    asm("{ .reg .u64 t; cvta.to.shared.u64 t, %1; cvt.u32.u64 %0, t; }"
        : "=r"(a) : "l"(p));
    return a;
}

__global__ __launch_bounds__(NTHREADS, 12)
void pcen_kernel(const float* __restrict__ x,
                 const float* __restrict__ alpha_p,
                 const float* __restrict__ power_p,
                 const float* __restrict__ bias_p,
                 float* __restrict__ out)
{
    const float s  = 0.015f;
    const float c1 = 0.985f;      // 1 - s
    const float EPSv = 1e-9f;

    __shared__ float4 tile[TILE_F4];
    __shared__ float  sW[NWARPS];

    const int tid  = threadIdx.x;
    const int lane = tid & 31;
    const int warp = tid >> 5;

    const size_t base = (size_t)blockIdx.x * T_LEN;
    const float4* xin = (const float4*)(x + base);
    float4* oout = (float4*)(out + base);

    // GMEM -> SMEM via cp.async: coalesced, no register staging.
    #pragma unroll
    for (int j = 0; j < 4; j++) {
        unsigned int dst = smem_u32(&tile[PAD_SLOT(j * NTHREADS + tid)]);
        const float4* src = &xin[j * NTHREADS + tid];
        asm volatile("cp.async.cg.shared.global [%0], [%1], 16;"
                     :: "r"(dst), "l"(src));
    }
    asm volatile("cp.async.commit_group;");

    // Scalars while the copy is in flight.
    const float alpha = __ldg(alpha_p);
    const float power = __ldg(power_p);
    const float bias  = __ldg(bias_p);

    asm volatile("cp.async.wait_group 0;");
    __syncthreads();   // bar1: tile(x) ready

    // Per-thread contiguous chunk: elements [tid*16, tid*16+16).
    float xv[PER_THREAD];
    #pragma unroll
    for (int j = 0; j < 4; j++) {
        float4 t4 = tile[PAD_SLOT(tid * 4 + j)];
        xv[4 * j + 0] = t4.x; xv[4 * j + 1] = t4.y;
        xv[4 * j + 2] = t4.z; xv[4 * j + 3] = t4.w;
    }

    // Thread-local scaled recurrence from zero (m' = M/s):
    // two independent 8-chains for ILP, merged with one FMA.
    float b0 = 0.f, b1 = 0.f;
    #pragma unroll
    for (int i = 0; i < 8; i++)  b0 = fmaf(c1, b0, xv[i]);
    #pragma unroll
    for (int i = 8; i < 16; i++) b1 = fmaf(c1, b1, xv[i]);

    // Decay powers.
    const float c2  = c1 * c1;
    const float c4  = c2 * c2;
    const float c8  = c4 * c4;       // c1^8
    const float a1  = c8 * c8;       // c1^16  (per-thread segment decay A)
    const float a2  = a1 * a1;       // A^2
    const float a4  = a2 * a2;       // A^4
    const float a8  = a4 * a4;       // A^8
    const float a16 = a8 * a8;       // A^16
    const float a32 = a16 * a16;     // A^32 (per-warp decay)

    float B = fmaf(b0, c8, b1);      // thread total

    // Inclusive Kogge-Stone warp scan: v_t = v_{t-d} * A^d + v_t
    float v = B;
    float u;
    u = __shfl_up_sync(0xffffffffu, v, 1);  if (lane >= 1)  v = fmaf(u, a1,  v);
    u = __shfl_up_sync(0xffffffffu, v, 2);  if (lane >= 2)  v = fmaf(u, a2,  v);
    u = __shfl_up_sync(0xffffffffu, v, 4);  if (lane >= 4)  v = fmaf(u, a4,  v);
    u = __shfl_up_sync(0xffffffffu, v, 8);  if (lane >= 8)  v = fmaf(u, a8,  v);
    u = __shfl_up_sync(0xffffffffu, v, 16); if (lane >= 16) v = fmaf(u, a16, v);

    if (lane == 31) sW[warp] = v;
    __syncthreads();   // bar2: sW ready

    // Cross-warp carry, computed redundantly per-thread (broadcast LDS):
    // carry_w = sum_{w'<w} sW[w'] * A32^(w-1-w')
    float carry = 0.f;
    #pragma unroll
    for (int w = 0; w < NWARPS - 1; w++)
        if (warp > w) carry = fmaf(carry, a32, sW[w]);

    float prev = __shfl_up_sync(0xffffffffu, v, 1);
    if (lane == 0) prev = 0.f;

    // A^lane by exact binary exponentiation.
    float p = 1.f;
    if (lane & 1)  p *= a1;
    if (lane & 2)  p *= a2;
    if (lane & 4)  p *= a4;
    if (lane & 8)  p *= a8;
    if (lane & 16) p *= a16;

    float m = fmaf(carry, p, prev);   // scaled state entering this segment

    const float nalpha = -alpha;
    const float bp = fast_ex2(power * fast_lg2(bias));   // bias^power

    // Epilogue (minimal form): per elem 2 FFMA + lg2/mul/ex2 + FFMA + lg2/mul/ex2 + FADD.
    #pragma unroll
    for (int j = 0; j < 4; j++) {
        float4 o4;
        float o[4];
        #pragma unroll
        for (int e = 0; e < 4; e++) {
            const int i = 4 * j + e;
            m = fmaf(c1, m, xv[i]);                       // m' recurrence
            float arg = fmaf(s, m, EPSv);                 // EPS + M
            float inv = fast_ex2(nalpha * fast_lg2(arg)); // (EPS+M)^(-alpha)
            float z = fmaf(xv[i], inv, bias);
            o[e] = fast_ex2(power * fast_lg2(z)) - bp;
        }
        o4.x = o[0]; o4.y = o[1]; o4.z = o[2]; o4.w = o[3];
        tile[PAD_SLOT(tid * 4 + j)] = o4;                 // stage for coalesced STG
    }
    __syncthreads();   // bar3: tile(o) ready

    oout[0 * NTHREADS + tid] = tile[PAD_SLOT(0 * NTHREADS + tid)];
    oout[1 * NTHREADS + tid] = tile[PAD_SLOT(1 * NTHREADS + tid)];
    oout[2 * NTHREADS + tid] = tile[PAD_SLOT(2 * NTHREADS + tid)];
    oout[3 * NTHREADS + tid] = tile[PAD_SLOT(3 * NTHREADS + tid)];
}

extern "C" void kernel_launch(void* const* d_in, const int* in_sizes, int n_in,
                              void* d_out, int out_size)
{
    const float* x     = (const float*)d_in[0];
    const float* alpha = (const float*)d_in[1];
    const float* power = (const float*)d_in[2];
    const float* bias  = (const float*)d_in[3];
    float* out = (float*)d_out;

    int rows = in_sizes[0] / T_LEN;   // B*F = 16384
    pcen_kernel<<<rows, NTHREADS>>>(x, alpha, power, bias, out);
}